// round 3
// baseline (speedup 1.0000x reference)
#include <cuda_runtime.h>

// ---------------- problem constants ----------------
#define NN 10000            // nodes
#define BB 64               // batch
#define DD 66               // input feature dim
#define OO 64               // output dim
#define MM 5                // num matrices = 2K+1
#define UU 320              // MM * OO
#define FF 4096             // BB * OO  (spmm feature width, node-major)
#define FF4 1024            // FF / 4
#define EMAX 200000
#define NFSZ ((size_t)NN * FF)

// ---------------- device scratch (static: no allocs allowed) ----------------
// g_Y holds 5 buffers of [N, B*O]: buf0=P, buf1=Y1, buf2=Y2, buf3=Y3, buf4=Y4
__device__ float g_Y[5ull * NN * FF];          // ~819 MB
__device__ int   g_rp[2][NN + 1];
__device__ int   g_cnt[2][NN];
__device__ int   g_cur[2][NN];
__device__ int   g_ecols[2][EMAX];
__device__ float g_evals[2][EMAX];

// ---------------- CSR build ----------------
__global__ void k_zero_cnt() {
    int i = blockIdx.x * blockDim.x + threadIdx.x;
    if (i < 2 * NN) ((int*)g_cnt)[i] = 0;
}

__global__ void k_hist(const int* __restrict__ rows, int E, int sup) {
    int e = blockIdx.x * blockDim.x + threadIdx.x;
    if (e < E) atomicAdd(&g_cnt[sup][rows[e]], 1);
}

__global__ void k_scan(int sup) {
    __shared__ int ssum[1024];
    const int* cnt = g_cnt[sup];
    int* rp  = g_rp[sup];
    int* cur = g_cur[sup];
    int t = threadIdx.x;
    int base = t * 10;
    int local[10];
    int sum = 0;
#pragma unroll
    for (int k = 0; k < 10; k++) {
        int i = base + k;
        int v = (i < NN) ? cnt[i] : 0;
        local[k] = sum;      // exclusive within this thread's span
        sum += v;
    }
    ssum[t] = sum;
    __syncthreads();
    // Hillis-Steele inclusive scan over 1024 thread sums
    for (int off = 1; off < 1024; off <<= 1) {
        int v = (t >= off) ? ssum[t - off] : 0;
        __syncthreads();
        ssum[t] += v;
        __syncthreads();
    }
    int prev = (t > 0) ? ssum[t - 1] : 0;
#pragma unroll
    for (int k = 0; k < 10; k++) {
        int i = base + k;
        if (i < NN) {
            int v = prev + local[k];
            rp[i]  = v;
            cur[i] = v;
        }
    }
    if (t == 1023) rp[NN] = ssum[1023];
}

__global__ void k_fill(const int* __restrict__ rows, const int* __restrict__ cols,
                       const float* __restrict__ vals, int E, int sup) {
    int e = blockIdx.x * blockDim.x + threadIdx.x;
    if (e < E) {
        int r = rows[e];
        int pos = atomicAdd(&g_cur[sup][r], 1);
        g_ecols[sup][pos] = cols[e];
        g_evals[sup][pos] = vals[e];
    }
}

// ---------------- GEMM0: Y_m = x0 @ W_m  (node-major outputs) ----------------
// block = 320 threads, handles 4 nodes sequentially.
// smem: sw[66*320] (folded weights: [Wp, W1, W2, W3, W4]), sx[64*66] (one node, all batches)
// thread tile: 8 batches x 8 outputs -> 64 fp32 accumulators.
#define GEMM_SMEM ((DD * UU + BB * DD) * 4)

__global__ void __launch_bounds__(320, 2)
k_gemm0(const float* __restrict__ x, const float* __restrict__ W,
        const float* __restrict__ bias) {
    extern __shared__ float sm[];
    float* sw = sm;                 // 21120 floats
    float* sx = sm + DD * UU;       // 4224 floats
    int t = threadIdx.x;

    // Build folded weight tile: u = m*64+o; m=0 -> W0 - W2 - W4 (for P)
    for (int idx = t; idx < DD * UU; idx += 320) {
        int d = idx / UU;
        int u = idx - d * UU;
        int m = u >> 6;
        int o = u & 63;
        float w;
        if (m == 0)
            w = W[(d * 5 + 0) * 64 + o] - W[(d * 5 + 2) * 64 + o] - W[(d * 5 + 4) * 64 + o];
        else
            w = W[(d * 5 + m) * 64 + o];
        sw[idx] = w;
    }

    int o_base = (t % 40) * 8;          // 40 output groups of 8
    int b_base = (t / 40) * 8;          // 8 batch groups of 8
    int bufIdx = o_base >> 6;
    int oo = o_base & 63;

    float binit[8];
#pragma unroll
    for (int k = 0; k < 8; k++)
        binit[k] = (bufIdx == 0) ? __ldg(&bias[oo + k]) : 0.f;

    for (int it = 0; it < 4; it++) {
        int n = blockIdx.x * 4 + it;
        __syncthreads();   // covers sw on first iter, protects sx reuse after
        for (int idx = t; idx < BB * DD; idx += 320) {
            int b = idx / DD;
            int dd = idx - b * DD;
            sx[idx] = x[(size_t)b * ((size_t)NN * DD) + (size_t)n * DD + dd];
        }
        __syncthreads();

        float acc[8][8];
#pragma unroll
        for (int j = 0; j < 8; j++)
#pragma unroll
            for (int k = 0; k < 8; k++)
                acc[j][k] = binit[k];

        const float* swp = sw + o_base;
#pragma unroll 2
        for (int d = 0; d < DD; d++) {
            float4 w0 = *(const float4*)&swp[d * UU];
            float4 w1 = *(const float4*)&swp[d * UU + 4];
            float xv[8];
#pragma unroll
            for (int j = 0; j < 8; j++)
                xv[j] = sx[(b_base + j) * DD + d];
#pragma unroll
            for (int j = 0; j < 8; j++) {
                acc[j][0] = fmaf(xv[j], w0.x, acc[j][0]);
                acc[j][1] = fmaf(xv[j], w0.y, acc[j][1]);
                acc[j][2] = fmaf(xv[j], w0.z, acc[j][2]);
                acc[j][3] = fmaf(xv[j], w0.w, acc[j][3]);
                acc[j][4] = fmaf(xv[j], w1.x, acc[j][4]);
                acc[j][5] = fmaf(xv[j], w1.y, acc[j][5]);
                acc[j][6] = fmaf(xv[j], w1.z, acc[j][6]);
                acc[j][7] = fmaf(xv[j], w1.w, acc[j][7]);
            }
        }

        float* dst = g_Y + (size_t)bufIdx * NFSZ + (size_t)n * FF + oo;
#pragma unroll
        for (int j = 0; j < 8; j++) {
            int b = b_base + j;
            float4 r0 = make_float4(acc[j][0], acc[j][1], acc[j][2], acc[j][3]);
            float4 r1 = make_float4(acc[j][4], acc[j][5], acc[j][6], acc[j][7]);
            *(float4*)&dst[b * 64]     = r0;
            *(float4*)&dst[b * 64 + 4] = r1;
        }
    }
}

// ---------------- SpMM (CSR gather) with fused epilogues ----------------
// MODE 0: out[r] = aux[r] + 2*acc   (T = Y_odd + 2*A*Y_even, in-place into aux buffer)
// MODE 1: out[r] = aux[r] +   acc   (S = P + A*T0, in-place into P)
// MODE 2: d_out  = aux[r] +   acc   (final, transposed to [B, N, O])
// grid = (NN rows, 8 feature chunks of 512 floats); chunk is the slow index
// so each 20 MB chunk of the gather source stays L2-resident across its wave.
template <int MODE>
__global__ void __launch_bounds__(128)
k_spmm(int sup, int srcBuf, int auxBuf, float* __restrict__ dout) {
    int r  = blockIdx.x;
    int fb = blockIdx.y * 128 + threadIdx.x;     // float4 index in [0, 1024)

    const int*   rp   = g_rp[sup];
    const int*   cols = g_ecols[sup];
    const float* vals = g_evals[sup];
    const float4* src4 = (const float4*)(g_Y + (size_t)srcBuf * NFSZ);
    const float4* aux4 = (const float4*)(g_Y + (size_t)auxBuf * NFSZ);

    int s = __ldg(&rp[r]);
    int e = __ldg(&rp[r + 1]);

    float ax = 0.f, ay = 0.f, az = 0.f, aw = 0.f;
    for (int i = s; i < e; i += 8) {
        int   cc[8];
        float vv[8];
#pragma unroll
        for (int j = 0; j < 8; j++) {
            int idx = i + j;
            bool ok = idx < e;
            cc[j] = ok ? __ldg(&cols[idx]) : 0;
            vv[j] = ok ? __ldg(&vals[idx]) : 0.f;
        }
#pragma unroll
        for (int j = 0; j < 8; j++) {
            float4 xv = __ldg(&src4[(size_t)cc[j] * FF4 + fb]);
            ax = fmaf(vv[j], xv.x, ax);
            ay = fmaf(vv[j], xv.y, ay);
            az = fmaf(vv[j], xv.z, az);
            aw = fmaf(vv[j], xv.w, aw);
        }
    }

    float4 a = __ldg(&aux4[(size_t)r * FF4 + fb]);
    float4 res;
    if (MODE == 0) {
        res.x = a.x + 2.f * ax; res.y = a.y + 2.f * ay;
        res.z = a.z + 2.f * az; res.w = a.w + 2.f * aw;
    } else {
        res.x = a.x + ax; res.y = a.y + ay;
        res.z = a.z + az; res.w = a.w + aw;
    }

    if (MODE == 2) {
        // feature f = b*64 + o ; write d_out[b][r*64 + o]
        int b  = fb >> 4;           // 16 float4 per batch
        int oq = fb & 15;
        ((float4*)dout)[(size_t)b * ((size_t)NN * 16) + (size_t)r * 16 + oq] = res;
    } else {
        // in-place into aux buffer (each row touched by exactly one block)
        float4* out4 = (float4*)(g_Y + (size_t)auxBuf * NFSZ);
        out4[(size_t)r * FF4 + fb] = res;
    }
}

// ---------------- launch ----------------
extern "C" void kernel_launch(void* const* d_in, const int* in_sizes, int n_in,
                              void* d_out, int out_size) {
    const float* inputs = (const float*)d_in[0];
    // d_in[1] = state (unused by forward)
    const float* weight = (const float*)d_in[2];
    const float* biases = (const float*)d_in[3];
    const float* vals0  = (const float*)d_in[4];
    const float* vals1  = (const float*)d_in[5];
    const int*   rows0  = (const int*)d_in[6];
    const int*   cols0  = (const int*)d_in[7];
    const int*   rows1  = (const int*)d_in[8];
    const int*   cols1  = (const int*)d_in[9];
    int E = in_sizes[4];

    cudaFuncSetAttribute(k_gemm0, cudaFuncAttributeMaxDynamicSharedMemorySize, GEMM_SMEM);

    int eb = (E + 255) / 256;

    // 1) CSR build (both supports)
    k_zero_cnt<<<(2 * NN + 255) / 256, 256>>>();
    k_hist<<<eb, 256>>>(rows0, E, 0);
    k_hist<<<eb, 256>>>(rows1, E, 1);
    k_scan<<<1, 1024>>>(0);
    k_scan<<<1, 1024>>>(1);
    k_fill<<<eb, 256>>>(rows0, cols0, vals0, E, 0);
    k_fill<<<eb, 256>>>(rows1, cols1, vals1, E, 1);

    // 2) Projection first (W commutes with the graph operator):
    //    P = x0*(W0-W2-W4)+bias, Y1..Y4 = x0*W1..W4   (node-major [N, B*O])
    k_gemm0<<<NN / 4, 320, GEMM_SMEM>>>(inputs, weight, biases);

    // 3) out = P + A0*(Y1 + 2*A0*Y2) + A1*(Y3 + 2*A1*Y4), 4 fused spmms
    dim3 sg(NN, FF / 512);
    k_spmm<0><<<sg, 128>>>(0, 2, 1, nullptr);          // Y1 <- Y1 + 2*A0*Y2   (=T0)
    k_spmm<1><<<sg, 128>>>(0, 1, 0, nullptr);          // P  <- P + A0*T0      (=S)
    k_spmm<0><<<sg, 128>>>(1, 4, 3, nullptr);          // Y3 <- Y3 + 2*A1*Y4   (=T1)
    k_spmm<2><<<sg, 128>>>(1, 3, 0, (float*)d_out);    // out = S + A1*T1  (transposed)
}